// round 17
// baseline (speedup 1.0000x reference)
#include <cuda_runtime.h>
#include <cuda_fp16.h>
#include <cstdint>

#define F_FACES 65536
#define N_ROWS  131072
#define C_CH    128
#define WDIM    512
#define KNB     9
#define KTOT    1152
#define NCHUNK  18
#define NSTAGE  3

// smem layout (gemm)
#define SM_SF      0            // 128*9*4 = 4608 B
#define SM_STAGES  5120         // 1024-aligned
#define STAGE_SZ   32768        // A 16K | B 16K
#define SMEM_TOTAL (SM_STAGES + NSTAGE * STAGE_SZ)   // 103424 B -> 2 CTAs/SM

// ---------------- device scratch ----------------
__device__ int   g_flags[2];
__device__ float g_styles[256];
__device__ float g_styles2[256];
__device__ float g_w2f[768];
__device__ __align__(16) __half g_cst_f16[F_FACES * C_CH];
__device__ __align__(16) __half g_Bmat_f16[2 * KTOT * C_CH];   // [b][kk][o], kk=k*128+i

// ---------------- ptx helpers (baseline sm_80+ only) ----------------
__device__ __forceinline__ uint32_t smem_u32(const void* p) {
    uint32_t a;
    asm("{ .reg .u64 t; cvta.to.shared.u64 t, %1; cvt.u32.u64 %0, t; }" : "=r"(a) : "l"(p));
    return a;
}
__device__ __forceinline__ void cpa16(uint32_t dst, const void* src, unsigned sz) {
    asm volatile("cp.async.cg.shared.global [%0], [%1], 16, %2;"
                 :: "r"(dst), "l"(src), "r"(sz) : "memory");
}
__device__ __forceinline__ void cpa_commit() {
    asm volatile("cp.async.commit_group;" ::: "memory");
}
template <int N>
__device__ __forceinline__ void cpa_wait() {
    asm volatile("cp.async.wait_group %0;" :: "n"(N) : "memory");
}
__device__ __forceinline__ void ldsm4(uint32_t* r, uint32_t addr) {
    asm volatile("ldmatrix.sync.aligned.m8n8.x4.shared.b16 {%0,%1,%2,%3}, [%4];"
                 : "=r"(r[0]), "=r"(r[1]), "=r"(r[2]), "=r"(r[3]) : "r"(addr));
}
__device__ __forceinline__ void ldsm4t(uint32_t* r, uint32_t addr) {
    asm volatile("ldmatrix.sync.aligned.m8n8.x4.trans.shared.b16 {%0,%1,%2,%3}, [%4];"
                 : "=r"(r[0]), "=r"(r[1]), "=r"(r[2]), "=r"(r[3]) : "r"(addr));
}
__device__ __forceinline__ void mma16816(float* c, const uint32_t* a, const uint32_t* b) {
    asm volatile("mma.sync.aligned.m16n8k16.row.col.f32.f16.f16.f32 "
                 "{%0,%1,%2,%3}, {%4,%5,%6,%7}, {%8,%9}, {%0,%1,%2,%3};"
                 : "+f"(c[0]), "+f"(c[1]), "+f"(c[2]), "+f"(c[3])
                 : "r"(a[0]), "r"(a[1]), "r"(a[2]), "r"(a[3]), "r"(b[0]), "r"(b[1]));
}

// ---------------- fused init: const->fp16 (0..8191) + styles (8192..8447) + probe (8448) ----------------
__global__ void init_kernel(const float* __restrict__ cst,
                            const float* __restrict__ ws,
                            const float* __restrict__ A1, const float* __restrict__ b1,
                            const float* __restrict__ A2, const float* __restrict__ b2,
                            const int* __restrict__ nbr,
                            const unsigned char* __restrict__ padb) {
    int t = threadIdx.x;
    int bid = blockIdx.x;
    if (bid < 8192) {
        int i = bid * 256 + t;   // *4 elements
        float4 v = ((const float4*)cst)[i];
        __half h[4];
        h[0] = __float2half_rn(v.x);
        h[1] = __float2half_rn(v.y);
        h[2] = __float2half_rn(v.z);
        h[3] = __float2half_rn(v.w);
        *(uint2*)(g_cst_f16 + 4 * (size_t)i) = *(uint2*)h;
        return;
    }
    if (bid == 8448) {
        __shared__ int s_or[2];
        if (t < 2) s_or[t] = 0;
        __syncthreads();
        int v = 0;
        if (t < 128) {
            for (int q = 0; q < 32; q++) { int j = t * 32 + q; v |= nbr[2 * j + 1]; }
            atomicOr(&s_or[0], v);
        } else {
            int tt = t - 128;
            for (int q = 0; q < 32; q++) { int idx = tt * 32 + q; if (idx & 3) v |= (int)padb[idx]; }
            atomicOr(&s_or[1], v);
        }
        __syncthreads();
        if (t == 0) { g_flags[0] = (s_or[0] == 0) ? 1 : 0; g_flags[1] = (s_or[1] == 0) ? 4 : 1; }
        return;
    }
    // styles: j in [0, 256)
    int j = bid - 8192;
    int b = j >> 7, i = j & 127;
    const float* w0 = ws + b * 2 * WDIM;
    const float* w1 = w0 + WDIM;
    const float* r1 = A1 + i * WDIM;
    const float* r2 = A2 + i * WDIM;
    float a1 = 0.f, a2 = 0.f;
    for (int jj = t; jj < WDIM; jj += 256) { a1 += w0[jj] * r1[jj]; a2 += w1[jj] * r2[jj]; }
    __shared__ float s1[256], s2[256];
    s1[t] = a1; s2[t] = a2;
    __syncthreads();
    for (int s = 128; s > 0; s >>= 1) {
        if (t < s) { s1[t] += s1[t + s]; s2[t] += s2[t + s]; }
        __syncthreads();
    }
    if (t == 0) {
        const float RSQ512 = 0.04419417382415922f;
        const float RSQ128 = 0.08838834764831845f;
        g_styles[j]  = s1[0] * RSQ512 + b1[i];
        g_styles2[j] = (s2[0] * RSQ512 + b2[i]) * RSQ128;
    }
}

// ---------------- demod + Bmat (fp16, [b][kk][o]) + w2f, one block per (b,o) ----------------
__global__ void demod_bmat_kernel(const float* __restrict__ w1, const float* __restrict__ w2) {
    int j = blockIdx.x;
    int b = j >> 7, o = j & 127;
    int i = threadIdx.x;
    float s = g_styles[b * 128 + i];
    const float* wp = w1 + o * KTOT + i * KNB;
    float wv[KNB];
    float sum = 0.f;
#pragma unroll
    for (int k = 0; k < KNB; k++) { wv[k] = wp[k] * s; sum += wv[k] * wv[k]; }
    __shared__ float sr[128];
    sr[i] = sum;
    __syncthreads();
    for (int st = 64; st > 0; st >>= 1) {
        if (i < st) sr[i] += sr[i + st];
        __syncthreads();
    }
    __shared__ float s_d;
    if (i == 0) s_d = rsqrtf(sr[0] + 1e-8f);
    __syncthreads();
    float d = s_d;
    __half* Bp = g_Bmat_f16 + ((size_t)b * KTOT) * C_CH + o;
#pragma unroll
    for (int k = 0; k < KNB; k++)
        Bp[(size_t)(k * 128 + i) * C_CH] = __float2half_rn(wv[k] * d);
    if (o < 3)
        g_w2f[b * 384 + o * 128 + i] = w2[o * 128 + i] * g_styles2[b * 128 + i];
}

// ---------------- chunk loader (cp.async), BK=64, 256 threads ----------------
__device__ __forceinline__ void load_chunk(
    int ck, uint32_t stage_base, const int* sf, int b, int t)
{
    int k = ck >> 1;
    int i0 = (ck & 1) << 6;
    uint32_t sA = stage_base;
    uint32_t sB = stage_base + 16384;
    const __half* Bp = g_Bmat_f16 + (size_t)b * KTOT * C_CH;
#pragma unroll
    for (int q = 0; q < 4; q++) {
        int v = t + 256 * q;                // 0..1023
        // A: m (128 rows) x granule g (0..7, 8 fp16 each); row stride 128B
        int m = v >> 3, g = v & 7;
        int f = sf[m * 9 + k];
        int fc = (f >= 0) ? f : 0;
        unsigned sz = (f >= 0) ? 16u : 0u;
        size_t so = (size_t)fc * C_CH + i0 + g * 8;
        uint32_t doff = m * 128 + (((g ^ (m & 7))) << 4);
        cpa16(sA + doff, g_cst_f16 + so, sz);
        // B: krow (64) x granule gn (0..15); row stride 256B
        int kr = v >> 4, gn = v & 15;
        uint32_t bo = kr * 256 + (((gn ^ (kr & 7))) << 4);
        size_t bso = (size_t)(ck * 64 + kr) * C_CH + gn * 8;
        cpa16(sB + bo, Bp + bso, 16u);
    }
    cpa_commit();
}

// ---------------- fp16 mma.sync GEMM, 8 warps, warp tile 64x32, single barrier/chunk ----------------
__global__ void __launch_bounds__(256, 2)
gemm_mma(const int* __restrict__ nbr,
         const unsigned char* __restrict__ padb,
         const float* __restrict__ noise_const,
         const float* __restrict__ noise_strength,
         const float* __restrict__ bias1,
         float* __restrict__ outx)
{
    extern __shared__ __align__(1024) char smem[];
    uint32_t sb = smem_u32(smem);
    int t = threadIdx.x;
    int warp = t >> 5, lane = t & 31;
    int row0 = blockIdx.x * 128;
    int b = row0 >> 16;

    // gather-index table
    int* sf = (int*)(smem + SM_SF);
    {
        int i64 = g_flags[0];
        int pstride = g_flags[1];
        for (int e = t; e < 128 * KNB; e += 256) {
            int m = e / 9, k = e - m * 9;
            int gi = (row0 + m) * 9 + k;
            int raw = i64 ? nbr[2 * gi] : nbr[gi];
            unsigned char pb = padb[gi * pstride];
            sf[e] = (pb == 0 && (unsigned)raw < (unsigned)N_ROWS) ? (raw & (F_FACES - 1)) : -1;
        }
    }
    __syncthreads();

    // prologue: stages 0..NSTAGE-2
#pragma unroll
    for (int s = 0; s < NSTAGE - 1; s++)
        load_chunk(s, sb + SM_STAGES + s * STAGE_SZ, sf, b, t);

    // warp tiling: 2 m-warps x 4 n-warps; warp tile 64(m) x 32(n)
    int wm = warp & 1, wn = warp >> 1;
    int grp = lane >> 3, lr = lane & 7;
    int mbase = wm * 64 + (grp & 1) * 8 + lr;
    int swz_a = mbase & 7;
    int kbase = (grp & 1) * 8 + lr;
    int gn_base = wn * 4 + (grp >> 1);

    float c[4][4][4];
#pragma unroll
    for (int mt = 0; mt < 4; mt++)
#pragma unroll
        for (int nt = 0; nt < 4; nt++)
#pragma unroll
            for (int r = 0; r < 4; r++) c[mt][nt][r] = 0.f;

    for (int ck = 0; ck < NCHUNK; ck++) {
        cpa_wait<NSTAGE - 2>();
        // Single barrier per chunk: RAW (cp.async visibility) and WAR (last
        // chunk's ldsm reads precede this barrier in program order).
        __syncthreads();
        int nc = ck + NSTAGE - 1;
        if (nc < NCHUNK)
            load_chunk(nc, sb + SM_STAGES + (nc % NSTAGE) * STAGE_SZ, sf, b, t);
        else
            cpa_commit();

        uint32_t stg = sb + SM_STAGES + (ck % NSTAGE) * STAGE_SZ;
        uint32_t aP = stg, bP = stg + 16384;

#pragma unroll
        for (int ks = 0; ks < 4; ks++) {
            uint32_t Af[4][4], Bf[2][4];
            int gk = ks * 2 + (grp >> 1);
#pragma unroll
            for (int mt = 0; mt < 4; mt++) {
                uint32_t off = (uint32_t)((mbase + mt * 16) * 128 + ((gk ^ swz_a) << 4));
                ldsm4(Af[mt], aP + off);
            }
#pragma unroll
            for (int ng = 0; ng < 2; ng++) {
                int krow = kbase + ks * 16;
                int gn = gn_base + ng * 2;
                uint32_t off = (uint32_t)(krow * 256 + ((gn ^ lr) << 4));
                ldsm4t(Bf[ng], bP + off);
            }
#pragma unroll
            for (int mt = 0; mt < 4; mt++)
#pragma unroll
                for (int nt = 0; nt < 4; nt++)
                    mma16816(c[mt][nt], Af[mt], &Bf[nt >> 1][(nt & 1) * 2]);
        }
    }

    // epilogue: + noise + bias1, lrelu(0.2), * sqrt(2), clip +-256
    float nstr = noise_strength[0];
    const float GAIN = 1.41421356237f;
#pragma unroll
    for (int mt = 0; mt < 4; mt++) {
        int r0 = row0 + wm * 64 + mt * 16 + (lane >> 2);
        int r1 = r0 + 8;
        float nz0 = noise_const[r0 & (F_FACES - 1)] * nstr;
        float nz1 = noise_const[r1 & (F_FACES - 1)] * nstr;
#pragma unroll
        for (int nt = 0; nt < 4; nt++) {
            int n0 = wn * 32 + nt * 8 + 2 * (lane & 3);
            float b0 = bias1[n0], b1v = bias1[n0 + 1];
            float v00 = c[mt][nt][0] + nz0 + b0;
            float v01 = c[mt][nt][1] + nz0 + b1v;
            float v10 = c[mt][nt][2] + nz1 + b0;
            float v11 = c[mt][nt][3] + nz1 + b1v;
            v00 = (v00 >= 0.f) ? v00 : 0.2f * v00;
            v01 = (v01 >= 0.f) ? v01 : 0.2f * v01;
            v10 = (v10 >= 0.f) ? v10 : 0.2f * v10;
            v11 = (v11 >= 0.f) ? v11 : 0.2f * v11;
            v00 = fminf(fmaxf(v00 * GAIN, -256.f), 256.f);
            v01 = fminf(fmaxf(v01 * GAIN, -256.f), 256.f);
            v10 = fminf(fmaxf(v10 * GAIN, -256.f), 256.f);
            v11 = fminf(fmaxf(v11 * GAIN, -256.f), 256.f);
            *(float2*)(outx + (size_t)r0 * C_CH + n0) = make_float2(v00, v01);
            *(float2*)(outx + (size_t)r1 * C_CH + n0) = make_float2(v10, v11);
        }
    }
}

// ---------------- second conv (128 -> 3): folded-output reduction (9 shuffles/row) ----------------
__global__ void img_kernel(const int* __restrict__ nbr,
                           const unsigned char* __restrict__ padb,
                           const float* __restrict__ x,
                           const float* __restrict__ bias2,
                           float* __restrict__ img)
{
    int t = threadIdx.x;
    int warp = t >> 5, lane = t & 31;
    int i64 = g_flags[0];
    int pstride = g_flags[1];
    // 64 rows per block -> batch index uniform per block (65536 % 64 == 0)
    int b = blockIdx.x >> 10;
    float4 w0 = *(const float4*)&g_w2f[b * 384 + 0 * 128 + lane * 4];
    float4 w1 = *(const float4*)&g_w2f[b * 384 + 1 * 128 + lane * 4];
    float4 w2v = *(const float4*)&g_w2f[b * 384 + 2 * 128 + lane * 4];
    int og = lane >> 3;                         // output index for this lane group (0..3)
    float b2g = bias2[og < 3 ? og : 0];         // valid for groups 0..2
    int nbase = blockIdx.x * 64 + warp * 8;
#pragma unroll
    for (int rr = 0; rr < 4; rr++) {
        int nA = nbase + rr * 2;
        int nB = nA + 1;
        int giA = nA * 9;
        int rawA = i64 ? nbr[2 * giA] : nbr[giA];
        bool vA = (padb[giA * pstride] == 0) && ((unsigned)rawA < (unsigned)N_ROWS);
        float4 xA = make_float4(0.f, 0.f, 0.f, 0.f);
        if (vA) xA = *(const float4*)(x + (size_t)rawA * 128 + lane * 4);
        int giB = nB * 9;
        int rawB = i64 ? nbr[2 * giB] : nbr[giB];
        bool vB = (padb[giB * pstride] == 0) && ((unsigned)rawB < (unsigned)N_ROWS);
        float4 xB = make_float4(0.f, 0.f, 0.f, 0.f);
        if (vB) xB = *(const float4*)(x + (size_t)rawB * 128 + lane * 4);

        float pA[3], pB[3];
        pA[0] = xA.x * w0.x + xA.y * w0.y + xA.z * w0.z + xA.w * w0.w;
        pB[0] = xB.x * w0.x + xB.y * w0.y + xB.z * w0.z + xB.w * w0.w;
        pA[1] = xA.x * w1.x + xA.y * w1.y + xA.z * w1.z + xA.w * w1.w;
        pB[1] = xB.x * w1.x + xB.y * w1.y + xB.z * w1.z + xB.w * w1.w;
        pA[2] = xA.x * w2v.x + xA.y * w2v.y + xA.z * w2v.z + xA.w * w2v.w;
        pB[2] = xB.x * w2v.x + xB.y * w2v.y + xB.z * w2v.z + xB.w * w2v.w;

        // levels d=16,8 on all 3 outputs (both rows interleaved)
#pragma unroll
        for (int d = 16; d >= 8; d >>= 1) {
#pragma unroll
            for (int o = 0; o < 3; o++) {
                pA[o] += __shfl_xor_sync(0xffffffffu, pA[o], d);
                pB[o] += __shfl_xor_sync(0xffffffffu, pB[o], d);
            }
        }
        // fold: lane group og takes output og (local select, no shuffle)
        float vAo = (og == 0) ? pA[0] : (og == 1) ? pA[1] : pA[2];
        float vBo = (og == 0) ? pB[0] : (og == 1) ? pB[1] : pB[2];
        // levels d=4,2,1 within 8-lane groups
#pragma unroll
        for (int d = 4; d > 0; d >>= 1) {
            vAo += __shfl_xor_sync(0xffffffffu, vAo, d);
            vBo += __shfl_xor_sync(0xffffffffu, vBo, d);
        }
        if (og < 3 && (lane & 7) == 0) {
            img[(size_t)nA * 3 + og] = fminf(fmaxf(vAo + b2g, -256.f), 256.f);
            img[(size_t)nB * 3 + og] = fminf(fmaxf(vBo + b2g, -256.f), 256.f);
        }
    }
}

// ---------------- launch ----------------
extern "C" void kernel_launch(void* const* d_in, const int* in_sizes, int n_in,
                              void* d_out, int out_size) {
    const int*           nbr  = (const int*)d_in[0];
    const unsigned char* padb = (const unsigned char*)d_in[1];
    const float* ws   = (const float*)d_in[2];
    const float* cst  = (const float*)d_in[3];
    const float* a1W  = (const float*)d_in[4];
    const float* a1b  = (const float*)d_in[5];
    const float* w1   = (const float*)d_in[6];
    const float* nco  = (const float*)d_in[7];
    const float* nst  = (const float*)d_in[8];
    const float* b1   = (const float*)d_in[9];
    const float* a2W  = (const float*)d_in[10];
    const float* a2b  = (const float*)d_in[11];
    const float* w2   = (const float*)d_in[12];
    const float* b2   = (const float*)d_in[13];
    float* outx = (float*)d_out;
    float* img  = outx + (size_t)N_ROWS * 128;

    static int inited = 0;
    if (!inited) {
        cudaFuncSetAttribute(gemm_mma, cudaFuncAttributeMaxDynamicSharedMemorySize, SMEM_TOTAL);
        inited = 1;
    }

    init_kernel<<<8449, 256>>>(cst, ws, a1W, a1b, a2W, a2b, nbr, padb);
    demod_bmat_kernel<<<256, 128>>>(w1, w2);
    gemm_mma<<<1024, 256, SMEM_TOTAL>>>(nbr, padb, nco, nst, b1, outx);
    img_kernel<<<2048, 256>>>(nbr, padb, outx, b2, img);
}